// round 14
// baseline (speedup 1.0000x reference)
#include <cuda_runtime.h>
#include <cstdint>

#define HW   14
#define NCH  128
#define NJ   32
#define NSP  896             // slice-pair tiles (2 slices each)
#define NBLK 740             // 370 CTAs per j-half; 148 SMs * 5 CTAs
#define THREADS 128

#define A_STRIDE 132         // words per A row (128 + 4 pad) -> conflict-free ldmatrix
#define A_ROWS   34          // 32 slot-rows + 2 tap-overrun rows
#define A_WORDS  (A_ROWS * A_STRIDE)      // 4488
#define B_STRIDE 132
#define B_ROWS   48                        // rows = kk*16 + jl (j-half only)
#define B_WORDS  (B_ROWS * B_STRIDE)      // 6336
#define SMEM_BYTES ((A_WORDS + B_WORDS) * 4)   // 43296 B -> 5 CTAs/SM

__device__ __align__(16) unsigned Wg[2 * B_ROWS * 128];   // tf32 W, [jh][kk*16+jl][i]
__device__ unsigned g_ctrA[32];           // counter for jh=0 (own 128B line)
__device__ unsigned g_ctrB[32];           // counter for jh=1

__global__ void prep_kernel(const float* __restrict__ W) {
    int idx = blockIdx.x * blockDim.x + threadIdx.x;
    if (idx == 0) { g_ctrA[0] = 0; g_ctrB[0] = 0; }
    if (idx < 2 * B_ROWS * 128) {
        int i   = idx & 127;
        int row = (idx >> 7) % B_ROWS;        // kk*16 + jl
        int jh  = idx / (B_ROWS * 128);
        int jl  = row & 15, kk = row >> 4;
        int j   = 16 * jh + jl;
        unsigned b;
        asm("cvt.rna.tf32.f32 %0, %1;" : "=r"(b) : "f"(W[j * 384 + kk * 128 + i]));
        Wg[idx] = b;
    }
}

__device__ __forceinline__ uint32_t smem_u32(const void* p) {
    uint32_t a;
    asm("{ .reg .u64 t; cvta.to.shared.u64 t, %1; cvt.u32.u64 %0, t; }" : "=r"(a) : "l"(p));
    return a;
}
__device__ __forceinline__ void ldsm_x4(uint32_t addr, unsigned& r0, unsigned& r1,
                                        unsigned& r2, unsigned& r3) {
    asm volatile("ldmatrix.sync.aligned.m8n8.x4.shared.b16 {%0,%1,%2,%3}, [%4];"
                 : "=r"(r0), "=r"(r1), "=r"(r2), "=r"(r3) : "r"(addr));
}
__device__ __forceinline__ void ldsm_x2(uint32_t addr, unsigned& r0, unsigned& r1) {
    asm volatile("ldmatrix.sync.aligned.m8n8.x2.shared.b16 {%0,%1}, [%2];"
                 : "=r"(r0), "=r"(r1) : "r"(addr));
}
__device__ __forceinline__ void mma_tf32(float* c, unsigned a0, unsigned a1, unsigned a2,
                                         unsigned a3, unsigned b0, unsigned b1) {
    asm volatile("mma.sync.aligned.m16n8k8.row.col.f32.tf32.tf32.f32 "
                 "{%0,%1,%2,%3}, {%4,%5,%6,%7}, {%8,%9}, {%0,%1,%2,%3};"
                 : "+f"(c[0]), "+f"(c[1]), "+f"(c[2]), "+f"(c[3])
                 : "r"(a0), "r"(a1), "r"(a2), "r"(a3), "r"(b0), "r"(b1));
}

// Prefetch one slice-pair's x rows for channel i into registers (streaming).
__device__ __forceinline__ void prefetch_x(const float* __restrict__ x, int sp, int i,
                                           float2 (&v)[2][7]) {
#pragma unroll
    for (int g = 0; g < 2; ++g) {
        int slice = sp * 2 + g;
        int n = slice / 14, h = slice % 14;
        const float2* xp = (const float2*)(x + ((n * NCH + i) * HW + h) * HW);
#pragma unroll
        for (int m2 = 0; m2 < 7; ++m2) v[g][m2] = __ldcs(xp + m2);
    }
}

__global__ void __launch_bounds__(THREADS)
conv_mma_kernel(const float* __restrict__ x, float* __restrict__ out) {
    extern __shared__ unsigned sm[];
    unsigned* Bs = sm;                        // [48][132]
    unsigned* As = sm + B_WORDS;              // [34][132]
    __shared__ int s_sp;

    const int t    = threadIdx.x;
    const int lane = t & 31;
    const int wid  = t >> 5;
    const int g    = wid & 1;                 // slice within pair
    const int jq   = wid >> 1;                // j-quarter within half
    const int jh   = (blockIdx.x >= NBLK / 2) ? 1 : 0;
    unsigned* ctr  = jh ? g_ctrB : g_ctrA;

    // ---- stage B half once (persistent CTA): 48 rows x 128 words, uint4 ----
    {
        const uint4* src = (const uint4*)(Wg + jh * B_ROWS * 128);
        for (int idx = t; idx < B_ROWS * 32; idx += THREADS) {
            int row = idx >> 5, seg = idx & 31;
            ((uint4*)(Bs + row * B_STRIDE))[seg] = src[(row << 5) + seg];
        }
    }
    // ---- zero the always-zero A rows: slots 0,15 of both slices + overrun ----
    {
        const int zr[6] = {0, 15, 16, 31, 32, 33};
        for (int idx = t; idx < 6 * 128; idx += THREADS)
            As[zr[idx >> 7] * A_STRIDE + (idx & 127)] = 0;
    }

    // fragment base addresses (constant across tiles)
    const uint32_t a_base = smem_u32(As) +
        (((16 * g + (lane & 15)) * A_STRIDE + 4 * (lane >> 4)) << 2);
    const uint32_t b_base = smem_u32(Bs) +
        (((8 * jq + (lane & 7)) * B_STRIDE + 4 * ((lane >> 3) & 1)) << 2);

    // ---- pure stealing: get first slice-pair ----
    if (t == 0) s_sp = atomicAdd(ctr, 1);
    __syncthreads();
    int sp = s_sp;
    float2 v[2][7];
    if (sp < NSP) prefetch_x(x, sp, t, v);

    while (sp < NSP) {
        __syncthreads();                      // A writable
        // ---- STS prefetched x -> A rows (16gg + p), col i = t ----
        {
            unsigned* col = As + t;
#pragma unroll
            for (int gg = 0; gg < 2; ++gg) {
                unsigned* base = col + (16 * gg) * A_STRIDE;
#pragma unroll
                for (int m2 = 0; m2 < 7; ++m2) {
                    int w0 = 2 * m2;
                    int p0 = w0 + 2;                     // even w never wraps
                    int p1 = (w0 == 12) ? 1 : (w0 + 3);  // w=13 wraps to slot 1
                    unsigned b0, b1;
                    asm("cvt.rna.tf32.f32 %0, %1;" : "=r"(b0) : "f"(v[gg][m2].x));
                    asm("cvt.rna.tf32.f32 %0, %1;" : "=r"(b1) : "f"(v[gg][m2].y));
                    base[p0 * A_STRIDE] = b0;            // banks (4p+i)%32: CF
                    base[p1 * A_STRIDE] = b1;
                }
            }
        }
        if (t == 0) s_sp = atomicAdd(ctr, 1);
        __syncthreads();                      // A ready + next sp visible
        int nxt = s_sp;
        if (nxt < NSP) prefetch_x(x, nxt, t, v);   // LDG overlaps compute

        // ---- compute: warp (g, jq) -> D[16m x 8j]; 3 taps x 16 k-chunks ----
        float acc[4];
#pragma unroll
        for (int a = 0; a < 4; ++a) acc[a] = 0.f;

#pragma unroll 1
        for (int kk = 0; kk < 3; ++kk) {
            uint32_t aa = a_base + kk * (A_STRIDE * 4);        // tap shift = +kk rows
            uint32_t bb = b_base + kk * (16 * B_STRIDE * 4);   // W tap block (16 rows)
#pragma unroll 8
            for (int q = 0; q < 16; ++q) {
                unsigned a0, a1, a2, a3, b0, b1;
                ldsm_x4(aa + q * 32, a0, a1, a2, a3);
                ldsm_x2(bb + q * 32, b0, b1);
                mma_tf32(acc, a0, a1, a2, a3, b0, b1);
            }
        }

        // ---- epilogue: scatter D with height-roll(+1); rows >= 14 discarded ----
        {
            int slice = sp * 2 + g;
            int n = slice / 14, h = slice % 14;
            int h2 = (h + 1 == 14) ? 0 : h + 1;
            int r0 = lane >> 2, r1 = r0 + 8;
            int j0 = 16 * jh + 8 * jq + 2 * (lane & 3);
            float* o0 = out + ((n * NJ + j0) * HW + h2) * HW;
            o0[r0]       = acc[0];
            o0[r0 + 196] = acc[1];            // j0+1
            if (r1 < 14) {
                o0[r1]       = acc[2];
                o0[r1 + 196] = acc[3];
            }
        }
        sp = nxt;
    }
}

extern "C" void kernel_launch(void* const* d_in, const int* in_sizes, int n_in,
                              void* d_out, int out_size) {
    const float* x = (const float*)d_in[0];   // (128,128,14,14) fp32
    const float* W = (const float*)d_in[1];   // (32,3,128) fp32
    float* out = (float*)d_out;               // (128,32,14,14) fp32

    prep_kernel<<<12, 1024>>>(W);

    cudaFuncSetAttribute(conv_mma_kernel,
                         cudaFuncAttributeMaxDynamicSharedMemorySize, SMEM_BYTES);
    conv_mma_kernel<<<NBLK, THREADS, SMEM_BYTES>>>(x, out);
}

// round 15
// speedup vs baseline: 1.4565x; 1.4565x over previous
#include <cuda_runtime.h>
#include <cstdint>

#define HW   14
#define NCH  128
#define NJ   32
#define NSP  896             // slice-pair tiles (2 slices each)
#define NBLK 148             // 1 CTA/SM; 2 half-pipelines per CTA
#define THREADS 256

#define A_STRIDE 132         // words per A row (128 + 4 pad) -> conflict-free ldmatrix
#define A_ROWS   34          // 32 slot-rows + 2 tap-overrun rows
#define A_WORDS  (A_ROWS * A_STRIDE)      // 4488 per buffer
#define B_STRIDE 132
#define B_WORDS  (96 * B_STRIDE)          // 12672 (rows = kk*32 + j)
#define SMEM_BYTES ((B_WORDS + 4 * A_WORDS) * 4)   // 122496 B -> 1 CTA/SM

__device__ __align__(16) unsigned Wg[96 * 128];   // tf32 W, row (kk*32+j), col i
__device__ unsigned g_ctr[32];

__global__ void prep_kernel(const float* __restrict__ W) {
    int idx = blockIdx.x * blockDim.x + threadIdx.x;
    if (idx == 0) g_ctr[0] = 2 * NBLK;    // static first tiles 0..295 pre-assigned
    if (idx < 96 * 128) {
        int i  = idx & 127;
        int j  = (idx >> 7) & 31;
        int kk = idx >> 12;
        unsigned b;
        asm("cvt.rna.tf32.f32 %0, %1;" : "=r"(b) : "f"(W[j * 384 + kk * 128 + i]));
        Wg[idx] = b;
    }
}

__device__ __forceinline__ uint32_t smem_u32(const void* p) {
    uint32_t a;
    asm("{ .reg .u64 t; cvta.to.shared.u64 t, %1; cvt.u32.u64 %0, t; }" : "=r"(a) : "l"(p));
    return a;
}
__device__ __forceinline__ void barh(int id) {
    asm volatile("bar.sync %0, 128;" :: "r"(id) : "memory");
}
__device__ __forceinline__ void ldsm_x4(uint32_t addr, unsigned& r0, unsigned& r1,
                                        unsigned& r2, unsigned& r3) {
    asm volatile("ldmatrix.sync.aligned.m8n8.x4.shared.b16 {%0,%1,%2,%3}, [%4];"
                 : "=r"(r0), "=r"(r1), "=r"(r2), "=r"(r3) : "r"(addr));
}
__device__ __forceinline__ void mma_tf32(float* c, unsigned a0, unsigned a1, unsigned a2,
                                         unsigned a3, unsigned b0, unsigned b1) {
    asm volatile("mma.sync.aligned.m16n8k8.row.col.f32.tf32.tf32.f32 "
                 "{%0,%1,%2,%3}, {%4,%5,%6,%7}, {%8,%9}, {%0,%1,%2,%3};"
                 : "+f"(c[0]), "+f"(c[1]), "+f"(c[2]), "+f"(c[3])
                 : "r"(a0), "r"(a1), "r"(a2), "r"(a3), "r"(b0), "r"(b1));
}

// Prefetch one slice-pair's x rows for channel i into registers (streaming).
__device__ __forceinline__ void prefetch_x(const float* __restrict__ x, int sp, int i,
                                           float2 (&v)[2][7]) {
#pragma unroll
    for (int g = 0; g < 2; ++g) {
        int slice = sp * 2 + g;
        int n = slice / 14, h = slice % 14;
        const float2* xp = (const float2*)(x + ((n * NCH + i) * HW + h) * HW);
#pragma unroll
        for (int m2 = 0; m2 < 7; ++m2) v[g][m2] = __ldcs(xp + m2);
    }
}

// STS one tile of x into an A buffer (this thread = channel i, column i).
__device__ __forceinline__ void stage_A(unsigned* As, int i, const float2 (&v)[2][7]) {
    unsigned* col = As + i;
#pragma unroll
    for (int gg = 0; gg < 2; ++gg) {
        unsigned* base = col + (16 * gg) * A_STRIDE;
#pragma unroll
        for (int m2 = 0; m2 < 7; ++m2) {
            int w0 = 2 * m2;
            int p0 = w0 + 2;                     // even w never wraps
            int p1 = (w0 == 12) ? 1 : (w0 + 3);  // w=13 wraps to slot 1
            unsigned b0, b1;
            asm("cvt.rna.tf32.f32 %0, %1;" : "=r"(b0) : "f"(v[gg][m2].x));
            asm("cvt.rna.tf32.f32 %0, %1;" : "=r"(b1) : "f"(v[gg][m2].y));
            base[p0 * A_STRIDE] = b0;            // banks (4p+i)%32: CF
            base[p1 * A_STRIDE] = b1;
        }
    }
}

__global__ void __launch_bounds__(THREADS)
conv_mma_kernel(const float* __restrict__ x, float* __restrict__ out) {
    extern __shared__ unsigned sm[];
    unsigned* Bs = sm;                        // [96][132]
    __shared__ int s_nxt[2][2];

    const int t    = threadIdx.x;
    const int lane = t & 31;
    const int hf   = t >> 7;                  // half-pipeline 0/1
    const int th   = t & 127;                 // thread (channel) within half
    const int wid2 = (t >> 5) & 3;
    const int g    = wid2 & 1;                // slice within pair
    const int nh   = wid2 >> 1;               // j-half

    unsigned* A0 = sm + B_WORDS + hf * (2 * A_WORDS);   // buffer 0
    unsigned* A1 = A0 + A_WORDS;                        // buffer 1

    // ---- stage B once (whole CTA) ----
    for (int idx = t; idx < 96 * 32; idx += THREADS) {
        int row = idx >> 5, seg = idx & 31;
        ((uint4*)(Bs + row * B_STRIDE))[seg] = ((const uint4*)(Wg + row * 128))[seg];
    }
    // ---- zero guard rows of BOTH buffers of this half ----
    {
        const int zr[6] = {0, 15, 16, 31, 32, 33};
        for (int idx = th; idx < 6 * 128; idx += 128) {
            int r = zr[idx >> 7], c = idx & 127;
            A0[r * A_STRIDE + c] = 0;
            A1[r * A_STRIDE + c] = 0;
        }
    }
    __syncthreads();

    const uint32_t a_off = ((16 * g + (lane & 15)) * A_STRIDE + 4 * (lane >> 4)) << 2;
    const uint32_t a_base0 = smem_u32(A0) + a_off;
    const uint32_t a_base1 = smem_u32(A1) + a_off;
    const uint32_t b_base = smem_u32(Bs) +
        (((16 * nh + 8 * (lane >> 4) + (lane & 7)) * B_STRIDE + 4 * ((lane >> 3) & 1)) << 2);

    // ---- prologue: static tile 0, steal tile 1 ----
    int cur = 2 * blockIdx.x + hf;            // 0..295 < NSP
    float2 v[2][7];
    prefetch_x(x, cur, th, v);
    stage_A(A0, th, v);
    if (th == 0) s_nxt[hf][0] = atomicAdd(&g_ctr[0], 1);
    barh(hf + 1);

    int pk = 0;
    while (cur < NSP) {
        int nxt = s_nxt[hf][pk];
        if (th == 0) s_nxt[hf][pk ^ 1] = atomicAdd(&g_ctr[0], 1);   // steal 2 ahead
        if (nxt < NSP) prefetch_x(x, nxt, th, v);    // LDG hides under compute

        // ---- compute tile cur from buf[pk]: 4 chains (q-parity split) ----
        float acc[16];
#pragma unroll
        for (int a = 0; a < 16; ++a) acc[a] = 0.f;
        uint32_t ab = pk ? a_base1 : a_base0;
#pragma unroll 1
        for (int kk = 0; kk < 3; ++kk) {
            uint32_t aa = ab + kk * (A_STRIDE * 4);            // tap shift = +kk rows
            uint32_t bb = b_base + kk * (32 * B_STRIDE * 4);   // W tap block
#pragma unroll 4
            for (int q = 0; q < 16; ++q) {
                unsigned a0, a1, a2, a3, b0, b1, b2, b3;
                ldsm_x4(aa + q * 32, a0, a1, a2, a3);
                ldsm_x4(bb + q * 32, b0, b1, b2, b3);
                float* c = acc + (q & 1) * 8;
                mma_tf32(c,     a0, a1, a2, a3, b0, b1);
                mma_tf32(c + 4, a0, a1, a2, a3, b2, b3);
            }
        }

        // ---- stage next tile into the other buffer (regs arrived during compute) ----
        if (nxt < NSP) stage_A(pk ? A0 : A1, th, v);

        // ---- epilogue: scatter with height-roll(+1); rows >= 14 discarded ----
        {
            int slice = cur * 2 + g;
            int n = slice / 14, h = slice % 14;
            int h2 = (h + 1 == 14) ? 0 : h + 1;
            int r0 = lane >> 2, r1 = r0 + 8;
#pragma unroll
            for (int tl = 0; tl < 2; ++tl) {
                int j0 = 16 * nh + 8 * tl + 2 * (lane & 3);
                float* o0 = out + ((n * NJ + j0) * HW + h2) * HW;
                o0[r0]       = acc[4 * tl + 0] + acc[4 * tl + 8];
                o0[r0 + 196] = acc[4 * tl + 1] + acc[4 * tl + 9];      // j0+1
                if (r1 < 14) {
                    o0[r1]       = acc[4 * tl + 2] + acc[4 * tl + 10];
                    o0[r1 + 196] = acc[4 * tl + 3] + acc[4 * tl + 11];
                }
            }
        }
        barh(hf + 1);                 // publish buf[pk^1] + s_nxt[pk^1]
        cur = nxt;
        pk ^= 1;
    }
}

extern "C" void kernel_launch(void* const* d_in, const int* in_sizes, int n_in,
                              void* d_out, int out_size) {
    const float* x = (const float*)d_in[0];   // (128,128,14,14) fp32
    const float* W = (const float*)d_in[1];   // (32,3,128) fp32
    float* out = (float*)d_out;               // (128,32,14,14) fp32

    prep_kernel<<<12, 1024>>>(W);

    cudaFuncSetAttribute(conv_mma_kernel,
                         cudaFuncAttributeMaxDynamicSharedMemorySize, SMEM_BYTES);
    conv_mma_kernel<<<NBLK, THREADS, SMEM_BYTES>>>(x, out);
}

// round 16
// speedup vs baseline: 1.6782x; 1.1522x over previous
#include <cuda_runtime.h>
#include <cstdint>

#define HW   14
#define NCH  128
#define NJ   32
#define NSP  896             // slice-pair tiles (2 slices each)
#define NBLK 148             // persistent, 1 CTA/SM
#define THREADS 384

#define A_STRIDE 132         // words per A row (128 + 4 pad) -> conflict-free ldmatrix
#define A_ROWS   34          // 32 slot-rows + 2 tap-overrun rows
#define A_WORDS  (A_ROWS * A_STRIDE)      // 4488 per buffer
#define B_STRIDE 132
#define B_WORDS  (96 * B_STRIDE)          // 12672 (rows = kk*32 + j); reused as scratch
#define SMEM_BYTES ((B_WORDS + 2 * A_WORDS) * 4)   // 86592 B

__device__ __align__(16) unsigned Wg[96 * 128];   // tf32 W, row (kk*32+j), col i
__device__ unsigned g_ctr[32];

__global__ void prep_kernel(const float* __restrict__ W) {
    int idx = blockIdx.x * blockDim.x + threadIdx.x;
    if (idx == 0) g_ctr[0] = NBLK;        // static first tiles 0..147 pre-assigned
    if (idx < 96 * 128) {
        int i  = idx & 127;
        int j  = (idx >> 7) & 31;
        int kk = idx >> 12;
        unsigned b;
        asm("cvt.rna.tf32.f32 %0, %1;" : "=r"(b) : "f"(W[j * 384 + kk * 128 + i]));
        Wg[idx] = b;
    }
}

__device__ __forceinline__ uint32_t smem_u32(const void* p) {
    uint32_t a;
    asm("{ .reg .u64 t; cvta.to.shared.u64 t, %1; cvt.u32.u64 %0, t; }" : "=r"(a) : "l"(p));
    return a;
}
__device__ __forceinline__ void ldsm_x4(uint32_t addr, unsigned& r0, unsigned& r1,
                                        unsigned& r2, unsigned& r3) {
    asm volatile("ldmatrix.sync.aligned.m8n8.x4.shared.b16 {%0,%1,%2,%3}, [%4];"
                 : "=r"(r0), "=r"(r1), "=r"(r2), "=r"(r3) : "r"(addr));
}
__device__ __forceinline__ void mma_tf32(float* c, unsigned a0, unsigned a1, unsigned a2,
                                         unsigned a3, unsigned b0, unsigned b1) {
    asm volatile("mma.sync.aligned.m16n8k8.row.col.f32.tf32.tf32.f32 "
                 "{%0,%1,%2,%3}, {%4,%5,%6,%7}, {%8,%9}, {%0,%1,%2,%3};"
                 : "+f"(c[0]), "+f"(c[1]), "+f"(c[2]), "+f"(c[3])
                 : "r"(a0), "r"(a1), "r"(a2), "r"(a3), "r"(b0), "r"(b1));
}

// Prefetch one slice's x row for channel i into registers (streaming).
__device__ __forceinline__ void prefetch_x(const float* __restrict__ x, int slice, int i,
                                           float2 (&v)[7]) {
    int n = slice / 14, h = slice % 14;
    const float2* xp = (const float2*)(x + ((n * NCH + i) * HW + h) * HW);
#pragma unroll
    for (int m2 = 0; m2 < 7; ++m2) v[m2] = __ldcs(xp + m2);
}

// STS one slice-row into an A buffer (thread = channel i, slot-group gg).
__device__ __forceinline__ void stage_A(unsigned* As, int i, int gg, const float2 (&v)[7]) {
    unsigned* base = As + (16 * gg) * A_STRIDE + i;
#pragma unroll
    for (int m2 = 0; m2 < 7; ++m2) {
        int w0 = 2 * m2;
        int p0 = w0 + 2;                     // even w never wraps
        int p1 = (w0 == 12) ? 1 : (w0 + 3);  // w=13 wraps to slot 1
        unsigned b0, b1;
        asm("cvt.rna.tf32.f32 %0, %1;" : "=r"(b0) : "f"(v[m2].x));
        asm("cvt.rna.tf32.f32 %0, %1;" : "=r"(b1) : "f"(v[m2].y));
        base[p0 * A_STRIDE] = b0;            // banks (4p+i)%32: CF
        base[p1 * A_STRIDE] = b1;
    }
}

__global__ void __launch_bounds__(THREADS)
conv_mma_kernel(const float* __restrict__ x, float* __restrict__ out) {
    extern __shared__ unsigned sm[];
    unsigned* Bs = sm;                        // [96][132]; later reused as scratch
    unsigned* A0 = sm + B_WORDS;
    unsigned* A1 = A0 + A_WORDS;
    float* scratch = (float*)sm;              // [pk][gid][slot][8 regs][32 lanes] = 4096 f
    __shared__ int s_nxt[2];

    const int t    = threadIdx.x;
    const int lane = t & 31;
    const int wid  = t >> 5;                  // 0..11
    const int g    = wid & 1;                 // slice within pair
    const int nh   = (wid >> 1) & 1;          // j-half
    const int kk   = wid >> 2;                // tap 0..2
    const int gid  = wid & 3;                 // reduction group (g, nh)
    const int si   = t & 127;                 // staging channel
    const int sg   = (t >> 7) & 1;            // staging slice (t<256 only)

    // ---- stage B to smem, zero A guard rows ----
    for (int idx = t; idx < 96 * 32; idx += THREADS) {
        int row = idx >> 5, seg = idx & 31;
        ((uint4*)(Bs + row * B_STRIDE))[seg] = ((const uint4*)(Wg + row * 128))[seg];
    }
    {
        const int zr[6] = {0, 15, 16, 31, 32, 33};
        for (int idx = t; idx < 6 * 128; idx += THREADS) {
            int r = zr[idx >> 7], c = idx & 127;
            A0[r * A_STRIDE + c] = 0;
            A1[r * A_STRIDE + c] = 0;
        }
    }
    __syncthreads();

    // ---- preload this warp's B fragments into registers (once per kernel) ----
    unsigned bf[16][4];
    {
        const uint32_t bb = smem_u32(Bs) +
            (((kk * 32 + 16 * nh + 8 * (lane >> 4) + (lane & 7)) * B_STRIDE +
              4 * ((lane >> 3) & 1)) << 2);
#pragma unroll
        for (int q = 0; q < 16; ++q)
            ldsm_x4(bb + q * 32, bf[q][0], bf[q][1], bf[q][2], bf[q][3]);
    }
    __syncthreads();                          // B reads done -> scratch overlay safe

    const uint32_t a_off = ((16 * g + (lane & 15)) * A_STRIDE + 4 * (lane >> 4)) << 2;
    const uint32_t a_base0 = smem_u32(A0) + a_off + kk * (A_STRIDE * 4);
    const uint32_t a_base1 = smem_u32(A1) + a_off + kk * (A_STRIDE * 4);

    // ---- prologue: static tile, stage A0, steal ahead ----
    int cur = blockIdx.x;                     // 0..147 < NSP
    float2 v[7];
    if (t < 256) {
        prefetch_x(x, cur * 2 + sg, si, v);
        stage_A(A0, si, sg, v);
    }
    if (t == 0) s_nxt[0] = atomicAdd(&g_ctr[0], 1);
    __syncthreads();

    int pk = 0;
    while (cur < NSP) {
        int nxt = s_nxt[pk];
        if (t == 0) s_nxt[pk ^ 1] = atomicAdd(&g_ctr[0], 1);      // steal 2 ahead
        if (nxt < NSP && t < 256) prefetch_x(x, nxt * 2 + sg, si, v);

        // ---- compute partial D (this tap only): 16 iters, B in regs, 4 chains ----
        float acc[16];
#pragma unroll
        for (int a = 0; a < 16; ++a) acc[a] = 0.f;
        const uint32_t aa = pk ? a_base1 : a_base0;
#pragma unroll
        for (int q = 0; q < 16; ++q) {
            unsigned a0, a1, a2, a3;
            ldsm_x4(aa + q * 32, a0, a1, a2, a3);
            float* c = acc + (q & 1) * 8;
            mma_tf32(c,     a0, a1, a2, a3, bf[q][0], bf[q][1]);
            mma_tf32(c + 4, a0, a1, a2, a3, bf[q][2], bf[q][3]);
        }
        float d[8];
#pragma unroll
        for (int a = 0; a < 8; ++a) d[a] = acc[a] + acc[a + 8];

        // ---- stage next tile into the other buffer ----
        if (nxt < NSP && t < 256) stage_A(pk ? A0 : A1, si, sg, v);

        // ---- partial store (2 non-reducer taps) ----
        const int rr = cur % 3;               // reducer tap for this tile
        if (kk != rr) {
            int slot = (kk + 3 - rr) % 3 - 1; // 0 or 1
            float* sp2 = scratch + ((pk * 4 + gid) * 2 + slot) * 256 + lane;
#pragma unroll
            for (int a = 0; a < 8; ++a) sp2[a * 32] = d[a];
        }
        __syncthreads();                      // publish A[pk^1], s_nxt, partials

        // ---- reducer tap: sum partials, scatter with height-roll(+1) ----
        if (kk == rr) {
            const float* sp2 = scratch + (pk * 4 + gid) * 2 * 256 + lane;
#pragma unroll
            for (int a = 0; a < 8; ++a) d[a] += sp2[a * 32] + sp2[256 + a * 32];
            int slice = cur * 2 + g;
            int n = slice / 14, h = slice % 14;
            int h2 = (h + 1 == 14) ? 0 : h + 1;
            int r0 = lane >> 2, r1 = r0 + 8;
#pragma unroll
            for (int tl = 0; tl < 2; ++tl) {
                int j0 = 16 * nh + 8 * tl + 2 * (lane & 3);
                float* o0 = out + ((n * NJ + j0) * HW + h2) * HW;
                o0[r0]       = d[4 * tl + 0];
                o0[r0 + 196] = d[4 * tl + 1];          // j0+1
                if (r1 < 14) {
                    o0[r1]       = d[4 * tl + 2];
                    o0[r1 + 196] = d[4 * tl + 3];
                }
            }
        }
        cur = nxt;
        pk ^= 1;
    }
}

extern "C" void kernel_launch(void* const* d_in, const int* in_sizes, int n_in,
                              void* d_out, int out_size) {
    const float* x = (const float*)d_in[0];   // (128,128,14,14) fp32
    const float* W = (const float*)d_in[1];   // (32,3,128) fp32
    float* out = (float*)d_out;               // (128,32,14,14) fp32

    prep_kernel<<<12, 1024>>>(W);

    cudaFuncSetAttribute(conv_mma_kernel,
                         cudaFuncAttributeMaxDynamicSharedMemorySize, SMEM_BYTES);
    conv_mma_kernel<<<NBLK, THREADS, SMEM_BYTES>>>(x, out);
}